// round 5
// baseline (speedup 1.0000x reference)
#include <cuda_runtime.h>
#include <cuda_bf16.h>
#include <math.h>
#include <stdint.h>

#define D_DIM 1024
#define F_DIM 4096
#define NHEADS 16
#define HD 64
#define MTOT 4096

typedef __nv_bfloat16 bf16;
typedef __nv_bfloat162 bf162;

// ---------------- scratch (no cudaMalloc allowed) ----------------
__device__ float g_q [4096u * 1024u];
__device__ float g_k [4096u * 1024u];
__device__ float g_v [4096u * 1024u];
__device__ float g_h [4096u * 1024u];
// bf16 hi/lo planes
__device__ __align__(256) bf16 g_y_hi   [4096u * 1024u];
__device__ __align__(256) bf16 g_y_lo   [4096u * 1024u];
__device__ __align__(256) bf16 g_at_hi  [4096u * 1024u];
__device__ __align__(256) bf16 g_at_lo  [4096u * 1024u];
__device__ __align__(256) bf16 g_y2_hi  [4096u * 1024u];
__device__ __align__(256) bf16 g_y2_lo  [4096u * 1024u];
__device__ __align__(256) bf16 g_ffn_hi [4096u * 4096u];
__device__ __align__(256) bf16 g_ffn_lo [4096u * 4096u];
// weights transposed [N][K]: wq(1M) wk(1M) wv(1M) wo(1M) w_in(4M) w_out(4M)
__device__ __align__(256) bf16 g_w_hi   [12u * 1024u * 1024u];
__device__ __align__(256) bf16 g_w_lo   [12u * 1024u * 1024u];

// ======================= helpers =======================
__device__ __forceinline__ uint32_t smem_u32(const void* p) {
    uint32_t a;
    asm("{ .reg .u64 t; cvta.to.shared.u64 t, %1; cvt.u32.u64 %0, t; }" : "=r"(a) : "l"(p));
    return a;
}
__device__ __forceinline__ void cp16(uint32_t dst, const void* src) {
    asm volatile("cp.async.cg.shared.global [%0], [%1], 16;" :: "r"(dst), "l"(src) : "memory");
}
#define CP_COMMIT() asm volatile("cp.async.commit_group;" ::: "memory")
__device__ __forceinline__ void ldsm4(uint32_t& r0, uint32_t& r1, uint32_t& r2, uint32_t& r3,
                                      uint32_t addr) {
    asm volatile("ldmatrix.sync.aligned.m8n8.x4.shared.b16 {%0,%1,%2,%3}, [%4];"
                 : "=r"(r0), "=r"(r1), "=r"(r2), "=r"(r3) : "r"(addr));
}
__device__ __forceinline__ void mma16816(float* d, const uint32_t* a, uint32_t b0, uint32_t b1) {
    asm volatile(
        "mma.sync.aligned.m16n8k16.row.col.f32.bf16.bf16.f32 "
        "{%0,%1,%2,%3}, {%4,%5,%6,%7}, {%8,%9}, {%0,%1,%2,%3};"
        : "+f"(d[0]), "+f"(d[1]), "+f"(d[2]), "+f"(d[3])
        : "r"(a[0]), "r"(a[1]), "r"(a[2]), "r"(a[3]), "r"(b0), "r"(b1));
}
__device__ __forceinline__ float gelu_tanh(float x) {
    float x3 = x * x * x;
    float t = tanhf(0.7978845608028654f * (x + 0.044715f * x3));
    return 0.5f * x * (1.0f + t);
}
// pack 2 floats -> hi bf162 + lo bf162
__device__ __forceinline__ void split2(float x, float y, uint32_t& hi, uint32_t& lo) {
    bf162 h = __floats2bfloat162_rn(x, y);
    float2 f = __bfloat1622float2(h);
    bf162 l = __floats2bfloat162_rn(x - f.x, y - f.y);
    hi = *(uint32_t*)&h; lo = *(uint32_t*)&l;
}

// ---------------- srmsnorm -> split planes ----------------
__global__ __launch_bounds__(256)
void srmsnorm_split_kernel(const float* __restrict__ x,
                           bf16* __restrict__ yhi, bf16* __restrict__ ylo) {
    const int row = blockIdx.x;
    const float4* xr = (const float4*)(x + (size_t)row * D_DIM);
    float4 v = xr[threadIdx.x];
    float ss = v.x * v.x + v.y * v.y + v.z * v.z + v.w * v.w;
    #pragma unroll
    for (int o = 16; o > 0; o >>= 1) ss += __shfl_xor_sync(0xffffffffu, ss, o);
    __shared__ float ws[8];
    if ((threadIdx.x & 31) == 0) ws[threadIdx.x >> 5] = ss;
    __syncthreads();
    float tot = ws[0] + ws[1] + ws[2] + ws[3] + ws[4] + ws[5] + ws[6] + ws[7];
    float s = 32.0f / fmaxf(sqrtf(tot), 1e-12f);
    v.x *= s; v.y *= s; v.z *= s; v.w *= s;
    uint2 hv, lv;
    split2(v.x, v.y, hv.x, lv.x);
    split2(v.z, v.w, hv.y, lv.y);
    size_t o = (size_t)row * D_DIM + threadIdx.x * 4;
    *(uint2*)(yhi + o) = hv;
    *(uint2*)(ylo + o) = lv;
}

// ---------------- transpose + split: dst[C][R] = split(src[R][C]^T) --------
__global__ __launch_bounds__(256)
void transpose_split_kernel(const float* __restrict__ src,
                            bf16* __restrict__ dhi, bf16* __restrict__ dlo,
                            int R, int C) {
    __shared__ float t[32][33];
    int bx = blockIdx.x * 32, by = blockIdx.y * 32;
    #pragma unroll
    for (int j = 0; j < 32; j += 8)
        t[threadIdx.y + j][threadIdx.x] = src[(size_t)(by + threadIdx.y + j) * C + bx + threadIdx.x];
    __syncthreads();
    #pragma unroll
    for (int j = 0; j < 32; j += 8) {
        float v = t[threadIdx.x][threadIdx.y + j];
        bf16 h = __float2bfloat16_rn(v);
        bf16 l = __float2bfloat16_rn(v - __bfloat162float(h));
        size_t o = (size_t)(bx + threadIdx.y + j) * R + by + threadIdx.x;
        dhi[o] = h; dlo[o] = l;
    }
}

// ============== HMMA bf16 hi/lo split GEMM, cp.async 3-stage ==============
// C = A @ Bt^T. Operands pre-split as bf16 hi/lo planes, K-major.
// smem tile row: [hi 64B | lo 64B | pad 16B] (ASTR=144), 128 rows per operand.
// EPI: 0 fp32 out; 1 gelu -> split planes out; 2 fp32 out + R
#define ASTR 144
#define TILEB (128 * ASTR)
#define STAGEB (2 * TILEB)
#define NSTG 3
#define GSMEM (NSTG * STAGEB)   // 110592

template<int EPI>
__global__ __launch_bounds__(256)
void gemm_cp(const bf16* __restrict__ Ahi, const bf16* __restrict__ Alo,
             const bf16* __restrict__ Bhi, const bf16* __restrict__ Blo,
             const float* __restrict__ R, float* __restrict__ C,
             bf16* __restrict__ Chi, bf16* __restrict__ Clo,
             int Nd, int Kd) {
    extern __shared__ char smem[];
    const uint32_t sbase = smem_u32(smem);
    const int tid = threadIdx.x;
    const int lane = tid & 31, wid = tid >> 5;
    const int row0 = blockIdx.y * 128, col0 = blockIdx.x * 128;
    const int wm0 = (wid >> 2) * 64;   // warp grid 2(m) x 4(n)
    const int wn0 = (wid & 3) * 32;

    float c[16][4];
    #pragma unroll
    for (int i = 0; i < 16; ++i)
        #pragma unroll
        for (int j = 0; j < 4; ++j) c[i][j] = 0.f;

    // cp.async mapping: thread -> (row = tid>>1, plane = tid&1), 4x16B per operand
    const int trow = tid >> 1, thalf = tid & 1;
    const bf16* srcA0 = (thalf ? Alo : Ahi) + (size_t)(row0 + trow) * Kd;
    const bf16* srcB0 = (thalf ? Blo : Bhi) + (size_t)(col0 + trow) * Kd;
    const uint32_t dstA0 = sbase + (uint32_t)trow * ASTR + thalf * 64;
    const uint32_t dstB0 = sbase + TILEB + (uint32_t)trow * ASTR + thalf * 64;

    auto issue = [&](int s) {
        const uint32_t off = (uint32_t)(s % NSTG) * STAGEB;
        const bf16* sa = srcA0 + s * 32;
        const bf16* sb = srcB0 + s * 32;
        cp16(dstA0 + off,      sa);
        cp16(dstA0 + off + 16, sa + 8);
        cp16(dstA0 + off + 32, sa + 16);
        cp16(dstA0 + off + 48, sa + 24);
        cp16(dstB0 + off,      sb);
        cp16(dstB0 + off + 16, sb + 8);
        cp16(dstB0 + off + 32, sb + 16);
        cp16(dstB0 + off + 48, sb + 24);
        CP_COMMIT();
    };

    const int stages = Kd / 32;
    issue(0); issue(1);

    const uint32_t lrow = (uint32_t)(lane & 15) * ASTR;
    const uint32_t lk   = (uint32_t)(lane >> 4) * 16;

    for (int s = 0; s < stages; ++s) {
        if (s + 1 < stages)
            asm volatile("cp.async.wait_group 1;" ::: "memory");
        else
            asm volatile("cp.async.wait_group 0;" ::: "memory");
        __syncthreads();
        if (s + 2 < stages) issue(s + 2);

        const uint32_t base = sbase + (uint32_t)(s % NSTG) * STAGEB;
        const uint32_t Ab = base + lrow + lk;
        const uint32_t Bb = base + TILEB + lrow + lk;
        #pragma unroll
        for (int kk = 0; kk < 2; ++kk) {
            const uint32_t kb = kk * 32;  // 16 bf16 = 32 bytes
            uint32_t ah[16], al[16], bh[8], bl[8];
            #pragma unroll
            for (int mt = 0; mt < 4; ++mt)
                ldsm4(ah[4*mt], ah[4*mt+1], ah[4*mt+2], ah[4*mt+3],
                      Ab + (uint32_t)(wm0 + mt * 16) * ASTR + kb);
            #pragma unroll
            for (int g = 0; g < 2; ++g)
                ldsm4(bh[4*g], bh[4*g+1], bh[4*g+2], bh[4*g+3],
                      Bb + (uint32_t)(wn0 + g * 16) * ASTR + kb);
            #pragma unroll
            for (int mt = 0; mt < 4; ++mt)
                #pragma unroll
                for (int nt = 0; nt < 4; ++nt) {
                    int bi = 4 * (nt >> 1) + (nt & 1);
                    mma16816(c[mt * 4 + nt], &ah[4 * mt], bh[bi], bh[bi + 2]);
                }
            #pragma unroll
            for (int mt = 0; mt < 4; ++mt)
                ldsm4(al[4*mt], al[4*mt+1], al[4*mt+2], al[4*mt+3],
                      Ab + (uint32_t)(wm0 + mt * 16) * ASTR + 64 + kb);
            #pragma unroll
            for (int mt = 0; mt < 4; ++mt)
                #pragma unroll
                for (int nt = 0; nt < 4; ++nt) {
                    int bi = 4 * (nt >> 1) + (nt & 1);
                    mma16816(c[mt * 4 + nt], &al[4 * mt], bh[bi], bh[bi + 2]);
                }
            #pragma unroll
            for (int g = 0; g < 2; ++g)
                ldsm4(bl[4*g], bl[4*g+1], bl[4*g+2], bl[4*g+3],
                      Bb + (uint32_t)(wn0 + g * 16) * ASTR + 64 + kb);
            #pragma unroll
            for (int mt = 0; mt < 4; ++mt)
                #pragma unroll
                for (int nt = 0; nt < 4; ++nt) {
                    int bi = 4 * (nt >> 1) + (nt & 1);
                    mma16816(c[mt * 4 + nt], &ah[4 * mt], bl[bi], bl[bi + 2]);
                }
        }
    }

    // epilogue
    const int mrow = row0 + wm0 + (lane >> 2);
    const int ncol = col0 + wn0 + (lane & 3) * 2;
    #pragma unroll
    for (int mt = 0; mt < 4; ++mt)
        #pragma unroll
        for (int nt = 0; nt < 4; ++nt) {
            const float* cc = c[mt * 4 + nt];
            const int m0 = mrow + mt * 16;
            const int n  = ncol + nt * 8;
            if (EPI == 1) {
                float g0 = gelu_tanh(cc[0]), g1 = gelu_tanh(cc[1]);
                float g2 = gelu_tanh(cc[2]), g3 = gelu_tanh(cc[3]);
                uint32_t h0, l0, h1, l1;
                split2(g0, g1, h0, l0);
                split2(g2, g3, h1, l1);
                *(uint32_t*)(Chi + (size_t)m0 * Nd + n) = h0;
                *(uint32_t*)(Clo + (size_t)m0 * Nd + n) = l0;
                *(uint32_t*)(Chi + (size_t)(m0 + 8) * Nd + n) = h1;
                *(uint32_t*)(Clo + (size_t)(m0 + 8) * Nd + n) = l1;
            } else {
                float2 r0 = make_float2(cc[0], cc[1]);
                float2 r1 = make_float2(cc[2], cc[3]);
                if (EPI == 2) {
                    float2 a0 = *(const float2*)(R + (size_t)m0 * Nd + n);
                    float2 a1 = *(const float2*)(R + (size_t)(m0 + 8) * Nd + n);
                    r0.x += a0.x; r0.y += a0.y;
                    r1.x += a1.x; r1.y += a1.y;
                }
                *(float2*)(C + (size_t)m0 * Nd + n) = r0;
                *(float2*)(C + (size_t)(m0 + 8) * Nd + n) = r1;
            }
        }
}

// ---------------- causal flash attention (fp32 SIMT, split-plane output) ----
__global__ __launch_bounds__(128)
void flash_attn(const float* __restrict__ Q, const float* __restrict__ K,
                const float* __restrict__ V,
                bf16* __restrict__ Ohi, bf16* __restrict__ Olo, int S) {
    __shared__ float4 Ks[64][16];
    __shared__ float4 Vs[64][16];
    const int b = blockIdx.z, h = blockIdx.y;
    const int qi = blockIdx.x * 128 + threadIdx.x;
    const size_t base = ((size_t)b * S) * D_DIM + (size_t)h * HD;

    const float4* qp = (const float4*)(Q + base + (size_t)qi * D_DIM);
    float4 q4[16];
    #pragma unroll
    for (int t = 0; t < 16; ++t) q4[t] = qp[t];
    float4 o4[16];
    #pragma unroll
    for (int t = 0; t < 16; ++t) o4[t] = make_float4(0.f, 0.f, 0.f, 0.f);

    float m = -1e30f, l = 0.f;
    const int ntiles = blockIdx.x * 2 + 2;

    for (int tile = 0; tile < ntiles; ++tile) {
        const int j0 = tile * 64;
        __syncthreads();
        #pragma unroll
        for (int i = 0; i < 8; ++i) {
            int f = i * 128 + threadIdx.x;
            int r = f >> 4, cc = f & 15;
            Ks[r][cc] = *(const float4*)(K + base + (size_t)(j0 + r) * D_DIM + cc * 4);
            Vs[r][cc] = *(const float4*)(V + base + (size_t)(j0 + r) * D_DIM + cc * 4);
        }
        __syncthreads();

        for (int jj = 0; jj < 64; jj += 8) {
            if (j0 + jj > qi) break;
            float p8[8];
            float mloc = m;
            #pragma unroll
            for (int e = 0; e < 8; ++e) {
                const int jl = jj + e;
                float s = 0.f;
                #pragma unroll
                for (int t = 0; t < 16; ++t) {
                    float4 kk = Ks[jl][t];
                    s = fmaf(q4[t].x, kk.x, s);
                    s = fmaf(q4[t].y, kk.y, s);
                    s = fmaf(q4[t].z, kk.z, s);
                    s = fmaf(q4[t].w, kk.w, s);
                }
                s *= 0.125f;
                if (j0 + jl > qi) s = -1e30f;
                p8[e] = s;
                mloc = fmaxf(mloc, s);
            }
            float alpha = __expf(m - mloc);
            m = mloc;
            float psum = 0.f;
            #pragma unroll
            for (int e = 0; e < 8; ++e) { p8[e] = __expf(p8[e] - m); psum += p8[e]; }
            l = l * alpha + psum;
            #pragma unroll
            for (int t = 0; t < 16; ++t) {
                float4 a = o4[t];
                a.x *= alpha; a.y *= alpha; a.z *= alpha; a.w *= alpha;
                #pragma unroll
                for (int e = 0; e < 8; ++e) {
                    float4 vv = Vs[jj + e][t];
                    float p = p8[e];
                    a.x = fmaf(p, vv.x, a.x);
                    a.y = fmaf(p, vv.y, a.y);
                    a.z = fmaf(p, vv.z, a.z);
                    a.w = fmaf(p, vv.w, a.w);
                }
                o4[t] = a;
            }
        }
    }

    const float inv = 1.0f / l;
    #pragma unroll
    for (int t = 0; t < 16; ++t) {
        float4 a = o4[t];
        a.x *= inv; a.y *= inv; a.z *= inv; a.w *= inv;
        uint2 hv, lv;
        split2(a.x, a.y, hv.x, lv.x);
        split2(a.z, a.w, hv.y, lv.y);
        size_t o = base + (size_t)qi * D_DIM + t * 4;
        *(uint2*)(Ohi + o) = hv;
        *(uint2*)(Olo + o) = lv;
    }
}

// ---------------- launch ----------------------------------------------------
extern "C" void kernel_launch(void* const* d_in, const int* in_sizes, int n_in,
                              void* d_out, int out_size) {
    const float* x     = (const float*)d_in[0];
    const float* wq    = (const float*)d_in[1];
    const float* wk    = (const float*)d_in[2];
    const float* wv    = (const float*)d_in[3];
    const float* wo    = (const float*)d_in[4];
    const float* w_in  = (const float*)d_in[5];
    const float* w_out = (const float*)d_in[6];
    float* out = (float*)d_out;

    const int Mtot = in_sizes[0] / D_DIM;   // 4096
    const int B = 2;
    const int S = Mtot / B;                 // 2048

    float *q, *k, *v, *h;
    bf16 *yhi, *ylo, *athi, *atlo, *y2hi, *y2lo, *fhi, *flo, *whi, *wlo;
    cudaGetSymbolAddress((void**)&q,    g_q);
    cudaGetSymbolAddress((void**)&k,    g_k);
    cudaGetSymbolAddress((void**)&v,    g_v);
    cudaGetSymbolAddress((void**)&h,    g_h);
    cudaGetSymbolAddress((void**)&yhi,  g_y_hi);
    cudaGetSymbolAddress((void**)&ylo,  g_y_lo);
    cudaGetSymbolAddress((void**)&athi, g_at_hi);
    cudaGetSymbolAddress((void**)&atlo, g_at_lo);
    cudaGetSymbolAddress((void**)&y2hi, g_y2_hi);
    cudaGetSymbolAddress((void**)&y2lo, g_y2_lo);
    cudaGetSymbolAddress((void**)&fhi,  g_ffn_hi);
    cudaGetSymbolAddress((void**)&flo,  g_ffn_lo);
    cudaGetSymbolAddress((void**)&whi,  g_w_hi);
    cudaGetSymbolAddress((void**)&wlo,  g_w_lo);

    bf16 *wqh = whi,                 *wql = wlo;
    bf16 *wkh = whi + 1024u*1024u,   *wkl = wlo + 1024u*1024u;
    bf16 *wvh = whi + 2u*1024u*1024u,*wvl = wlo + 2u*1024u*1024u;
    bf16 *woh = whi + 3u*1024u*1024u,*wol = wlo + 3u*1024u*1024u;
    bf16 *wih = whi + 4u*1024u*1024u,*wil = wlo + 4u*1024u*1024u;  // [4096][1024]
    bf16 *wuh = whi + 8u*1024u*1024u,*wul = wlo + 8u*1024u*1024u;  // [1024][4096]

    cudaFuncSetAttribute(gemm_cp<0>, cudaFuncAttributeMaxDynamicSharedMemorySize, GSMEM);
    cudaFuncSetAttribute(gemm_cp<1>, cudaFuncAttributeMaxDynamicSharedMemorySize, GSMEM);
    cudaFuncSetAttribute(gemm_cp<2>, cudaFuncAttributeMaxDynamicSharedMemorySize, GSMEM);

    // weight transpose+split -> [N][K] bf16 hi/lo
    dim3 tb(32, 8);
    transpose_split_kernel<<<dim3(32, 32), tb>>>(wq, wqh, wql, 1024, 1024);
    transpose_split_kernel<<<dim3(32, 32), tb>>>(wk, wkh, wkl, 1024, 1024);
    transpose_split_kernel<<<dim3(32, 32), tb>>>(wv, wvh, wvl, 1024, 1024);
    transpose_split_kernel<<<dim3(32, 32), tb>>>(wo, woh, wol, 1024, 1024);
    transpose_split_kernel<<<dim3(128, 32), tb>>>(w_in, wih, wil, 1024, 4096);
    transpose_split_kernel<<<dim3(32, 128), tb>>>(w_out, wuh, wul, 4096, 1024);

    // 1. y = srmsnorm(x) -> planes
    srmsnorm_split_kernel<<<Mtot, 256>>>(x, yhi, ylo);

    // 2. q,k,v = y @ w
    dim3 gD(D_DIM / 128, Mtot / 128);        // (8, 32)
    gemm_cp<0><<<gD, 256, GSMEM>>>(yhi, ylo, wqh, wql, nullptr, q, nullptr, nullptr, D_DIM, D_DIM);
    gemm_cp<0><<<gD, 256, GSMEM>>>(yhi, ylo, wkh, wkl, nullptr, k, nullptr, nullptr, D_DIM, D_DIM);
    gemm_cp<0><<<gD, 256, GSMEM>>>(yhi, ylo, wvh, wvl, nullptr, v, nullptr, nullptr, D_DIM, D_DIM);

    // 3. attention -> split planes
    dim3 ga(S / 128, NHEADS, B);
    flash_attn<<<ga, 128>>>(q, k, v, athi, atlo, S);

    // 4. h = attn @ wo + x
    gemm_cp<2><<<gD, 256, GSMEM>>>(athi, atlo, woh, wol, x, h, nullptr, nullptr, D_DIM, D_DIM);

    // 5. y2 = srmsnorm(h) -> planes
    srmsnorm_split_kernel<<<Mtot, 256>>>(h, y2hi, y2lo);

    // 6. ffn = gelu(y2 @ w_in) -> split planes
    dim3 gF(F_DIM / 128, Mtot / 128);        // (32, 32)
    gemm_cp<1><<<gF, 256, GSMEM>>>(y2hi, y2lo, wih, wil, nullptr, nullptr, fhi, flo, F_DIM, D_DIM);

    // 7. out = ffn @ w_out + h
    gemm_cp<2><<<gD, 256, GSMEM>>>(fhi, flo, wuh, wul, h, out, nullptr, nullptr, D_DIM, F_DIM);
}

// round 7
// speedup vs baseline: 1.8233x; 1.8233x over previous
#include <cuda_runtime.h>
#include <cuda_bf16.h>
#include <math.h>
#include <stdint.h>

#define D_DIM 1024
#define F_DIM 4096
#define NHEADS 16
#define HD 64

typedef __nv_bfloat16 bf16;
typedef __nv_bfloat162 bf162;

// ---------------- scratch (no cudaMalloc allowed) ----------------
__device__ float g_y   [4096u * 1024u];
__device__ __align__(256) float g_q   [4096u * 1024u];  // holds q_hi/q_lo bf16 planes
__device__ __align__(256) float g_k   [4096u * 1024u];  // k_hi/k_lo
__device__ __align__(256) float g_v   [4096u * 1024u];  // v_hi/v_lo (lo unused)
__device__ float g_attn[4096u * 1024u];
__device__ float g_h   [4096u * 1024u];
__device__ float g_y2  [4096u * 1024u];
__device__ float g_ffn [4096u * 4096u];
__device__ float g_wt  [12u * 1024u * 1024u];

// ======================= helpers =======================
__device__ __forceinline__ uint32_t smem_u32(const void* p) {
    uint32_t a;
    asm("{ .reg .u64 t; cvta.to.shared.u64 t, %1; cvt.u32.u64 %0, t; }" : "=r"(a) : "l"(p));
    return a;
}
__device__ __forceinline__ void cp16(uint32_t dst, const void* src) {
    asm volatile("cp.async.cg.shared.global [%0], [%1], 16;" :: "r"(dst), "l"(src) : "memory");
}
#define CP_COMMIT() asm volatile("cp.async.commit_group;" ::: "memory")
#define CP_WAIT0()  asm volatile("cp.async.wait_group 0;" ::: "memory")
__device__ __forceinline__ void ldsm4(uint32_t& r0, uint32_t& r1, uint32_t& r2, uint32_t& r3,
                                      uint32_t addr) {
    asm volatile("ldmatrix.sync.aligned.m8n8.x4.shared.b16 {%0,%1,%2,%3}, [%4];"
                 : "=r"(r0), "=r"(r1), "=r"(r2), "=r"(r3) : "r"(addr));
}
__device__ __forceinline__ void ldsm4t(uint32_t& r0, uint32_t& r1, uint32_t& r2, uint32_t& r3,
                                       uint32_t addr) {
    asm volatile("ldmatrix.sync.aligned.m8n8.x4.trans.shared.b16 {%0,%1,%2,%3}, [%4];"
                 : "=r"(r0), "=r"(r1), "=r"(r2), "=r"(r3) : "r"(addr));
}
__device__ __forceinline__ void mma16816(float* d, const uint32_t* a, uint32_t b0, uint32_t b1) {
    asm volatile(
        "mma.sync.aligned.m16n8k16.row.col.f32.bf16.bf16.f32 "
        "{%0,%1,%2,%3}, {%4,%5,%6,%7}, {%8,%9}, {%0,%1,%2,%3};"
        : "+f"(d[0]), "+f"(d[1]), "+f"(d[2]), "+f"(d[3])
        : "r"(a[0]), "r"(a[1]), "r"(a[2]), "r"(a[3]), "r"(b0), "r"(b1));
}
__device__ __forceinline__ void split4(float4 v, uint2& hi, uint2& lo) {
    bf162 h01 = __floats2bfloat162_rn(v.x, v.y);
    bf162 h23 = __floats2bfloat162_rn(v.z, v.w);
    float2 f01 = __bfloat1622float2(h01);
    float2 f23 = __bfloat1622float2(h23);
    bf162 l01 = __floats2bfloat162_rn(v.x - f01.x, v.y - f01.y);
    bf162 l23 = __floats2bfloat162_rn(v.z - f23.x, v.w - f23.y);
    hi.x = *(uint32_t*)&h01; hi.y = *(uint32_t*)&h23;
    lo.x = *(uint32_t*)&l01; lo.y = *(uint32_t*)&l23;
}
__device__ __forceinline__ void split2(float x, float y, uint32_t& hi, uint32_t& lo) {
    bf162 h = __floats2bfloat162_rn(x, y);
    float2 f = __bfloat1622float2(h);
    bf162 l = __floats2bfloat162_rn(x - f.x, y - f.y);
    hi = *(uint32_t*)&h; lo = *(uint32_t*)&l;
}
__device__ __forceinline__ uint32_t packbf(float a, float b) {
    bf162 h = __floats2bfloat162_rn(a, b);
    return *(uint32_t*)&h;
}
__device__ __forceinline__ float gelu_tanh(float x) {
    float x3 = x * x * x;
    float t = tanhf(0.7978845608028654f * (x + 0.044715f * x3));
    return 0.5f * x * (1.0f + t);
}

// ---------------- srmsnorm (fp32 out) ----------------
__global__ __launch_bounds__(256)
void srmsnorm_kernel(const float* __restrict__ x, float* __restrict__ y) {
    const int row = blockIdx.x;
    const float4* xr = (const float4*)(x + (size_t)row * D_DIM);
    float4 v = xr[threadIdx.x];
    float ss = v.x * v.x + v.y * v.y + v.z * v.z + v.w * v.w;
    #pragma unroll
    for (int o = 16; o > 0; o >>= 1) ss += __shfl_xor_sync(0xffffffffu, ss, o);
    __shared__ float ws[8];
    if ((threadIdx.x & 31) == 0) ws[threadIdx.x >> 5] = ss;
    __syncthreads();
    float tot = ws[0] + ws[1] + ws[2] + ws[3] + ws[4] + ws[5] + ws[6] + ws[7];
    float s = 32.0f / fmaxf(sqrtf(tot), 1e-12f);
    float4* yr = (float4*)(y + (size_t)row * D_DIM);
    v.x *= s; v.y *= s; v.z *= s; v.w *= s;
    yr[threadIdx.x] = v;
}

// ---------------- transpose ----------------
__global__ __launch_bounds__(256)
void transpose_kernel(const float* __restrict__ src, float* __restrict__ dst, int R, int C) {
    __shared__ float t[32][33];
    int bx = blockIdx.x * 32, by = blockIdx.y * 32;
    #pragma unroll
    for (int j = 0; j < 32; j += 8)
        t[threadIdx.y + j][threadIdx.x] = src[(size_t)(by + threadIdx.y + j) * C + bx + threadIdx.x];
    __syncthreads();
    #pragma unroll
    for (int j = 0; j < 32; j += 8)
        dst[(size_t)(bx + threadIdx.y + j) * R + by + threadIdx.x] = t[threadIdx.x][threadIdx.y + j];
}

// ============== HMMA bf16 hi/lo split GEMM (R4 structure, proven) ==============
// EPI: 0 fp32 out; 1 gelu fp32 out; 2 fp32 out + residual R; 3 scale -> bf16 hi/lo planes
#define ASTR 144
#define TILEB (128 * ASTR)
#define GSMEM (4 * TILEB)   // 73728

template<int EPI>
__global__ __launch_bounds__(256)
void gemm_mma(const float* __restrict__ A, const float* __restrict__ Bt,
              const float* __restrict__ R, float* __restrict__ C,
              bf16* __restrict__ Chi, bf16* __restrict__ Clo, float scale,
              int Nd, int Kd) {
    extern __shared__ char smem[];
    const uint32_t sbase = smem_u32(smem);
    const int tid = threadIdx.x;
    const int lane = tid & 31, wid = tid >> 5;
    const int row0 = blockIdx.y * 128, col0 = blockIdx.x * 128;
    const int wm0 = (wid >> 2) * 64;
    const int wn0 = (wid & 3) * 32;

    const uint32_t SA[2] = { sbase,         sbase + 2 * TILEB };
    const uint32_t SB[2] = { sbase + TILEB, sbase + 3 * TILEB };

    float c[16][4];
    #pragma unroll
    for (int i = 0; i < 16; ++i)
        #pragma unroll
        for (int j = 0; j < 4; ++j) c[i][j] = 0.f;

    const int gr = tid >> 3;
    const int gq = tid & 7;
    const float* Agl = A  + (size_t)(row0 + gr) * Kd + gq * 4;
    const float* Bgl = Bt + (size_t)(col0 + gr) * Kd + gq * 4;

    float4 va[4], vb[4];
    auto ldg = [&](int s) {
        const int k0 = s * 32;
        #pragma unroll
        for (int i = 0; i < 4; ++i) {
            va[i] = *(const float4*)(Agl + (size_t)(i * 32) * Kd + k0);
            vb[i] = *(const float4*)(Bgl + (size_t)(i * 32) * Kd + k0);
        }
    };
    auto sts = [&](int b) {
        char* da = smem + (b ? 2 * TILEB : 0);
        char* db = smem + (b ? 3 * TILEB : TILEB);
        #pragma unroll
        for (int i = 0; i < 4; ++i) {
            uint2 hi, lo;
            int off = (gr + i * 32) * ASTR + gq * 8;
            split4(va[i], hi, lo);
            *(uint2*)(da + off) = hi;
            *(uint2*)(da + off + 64) = lo;
            split4(vb[i], hi, lo);
            *(uint2*)(db + off) = hi;
            *(uint2*)(db + off + 64) = lo;
        }
    };

    const uint32_t lrow = (uint32_t)(lane & 15) * ASTR;
    const uint32_t lk   = (uint32_t)(lane >> 4) * 16;
    const int stages = Kd / 32;

    ldg(0); sts(0); __syncthreads();

    for (int s = 0; s < stages; ++s) {
        const int b = s & 1;
        if (s + 1 < stages) ldg(s + 1);

        const uint32_t Ab = SA[b] + lrow + lk;
        const uint32_t Bb = SB[b] + lrow + lk;
        #pragma unroll
        for (int kk = 0; kk < 2; ++kk) {
            const uint32_t kb = kk * 32;
            uint32_t ah[16], al[16], bh[8], bl[8];
            #pragma unroll
            for (int mt = 0; mt < 4; ++mt)
                ldsm4(ah[4*mt], ah[4*mt+1], ah[4*mt+2], ah[4*mt+3],
                      Ab + (uint32_t)(wm0 + mt * 16) * ASTR + kb);
            #pragma unroll
            for (int g = 0; g < 2; ++g)
                ldsm4(bh[4*g], bh[4*g+1], bh[4*g+2], bh[4*g+3],
                      Bb + (uint32_t)(wn0 + g * 16) * ASTR + kb);
            #pragma unroll
            for (int mt = 0; mt < 4; ++mt)
                #pragma unroll
                for (int nt = 0; nt < 4; ++nt) {
                    int bi = 4 * (nt >> 1) + (nt & 1);
                    mma16816(c[mt * 4 + nt], &ah[4 * mt], bh[bi], bh[bi + 2]);
                }
            #pragma unroll
            for (int mt = 0; mt < 4; ++mt)
                ldsm4(al[4*mt], al[4*mt+1], al[4*mt+2], al[4*mt+3],
                      Ab + (uint32_t)(wm0 + mt * 16) * ASTR + 64 + kb);
            #pragma unroll
            for (int mt = 0; mt < 4; ++mt)
                #pragma unroll
                for (int nt = 0; nt < 4; ++nt) {
                    int bi = 4 * (nt >> 1) + (nt & 1);
                    mma16816(c[mt * 4 + nt], &al[4 * mt], bh[bi], bh[bi + 2]);
                }
            #pragma unroll
            for (int g = 0; g < 2; ++g)
                ldsm4(bl[4*g], bl[4*g+1], bl[4*g+2], bl[4*g+3],
                      Bb + (uint32_t)(wn0 + g * 16) * ASTR + 64 + kb);
            #pragma unroll
            for (int mt = 0; mt < 4; ++mt)
                #pragma unroll
                for (int nt = 0; nt < 4; ++nt) {
                    int bi = 4 * (nt >> 1) + (nt & 1);
                    mma16816(c[mt * 4 + nt], &ah[4 * mt], bl[bi], bl[bi + 2]);
                }
        }
        __syncthreads();
        if (s + 1 < stages) { sts(b ^ 1); __syncthreads(); }
    }

    const int mrow = row0 + wm0 + (lane >> 2);
    const int ncol = col0 + wn0 + (lane & 3) * 2;
    #pragma unroll
    for (int mt = 0; mt < 4; ++mt)
        #pragma unroll
        for (int nt = 0; nt < 4; ++nt) {
            const float* cc = c[mt * 4 + nt];
            const int m0 = mrow + mt * 16;
            const int n  = ncol + nt * 8;
            if (EPI == 3) {
                uint32_t h0, l0, h1, l1;
                split2(cc[0] * scale, cc[1] * scale, h0, l0);
                split2(cc[2] * scale, cc[3] * scale, h1, l1);
                *(uint32_t*)(Chi + (size_t)m0 * Nd + n) = h0;
                *(uint32_t*)(Clo + (size_t)m0 * Nd + n) = l0;
                *(uint32_t*)(Chi + (size_t)(m0 + 8) * Nd + n) = h1;
                *(uint32_t*)(Clo + (size_t)(m0 + 8) * Nd + n) = l1;
            } else {
                float2 r0 = make_float2(cc[0], cc[1]);
                float2 r1 = make_float2(cc[2], cc[3]);
                if (EPI == 1) {
                    r0.x = gelu_tanh(r0.x); r0.y = gelu_tanh(r0.y);
                    r1.x = gelu_tanh(r1.x); r1.y = gelu_tanh(r1.y);
                }
                if (EPI == 2) {
                    float2 a0 = *(const float2*)(R + (size_t)m0 * Nd + n);
                    float2 a1 = *(const float2*)(R + (size_t)(m0 + 8) * Nd + n);
                    r0.x += a0.x; r0.y += a0.y;
                    r1.x += a1.x; r1.y += a1.y;
                }
                *(float2*)(C + (size_t)m0 * Nd + n) = r0;
                *(float2*)(C + (size_t)(m0 + 8) * Nd + n) = r1;
            }
        }
}

// ================= mma causal flash attention =================
// grid (S/64, H, B), 128 thr (4 warps x 16 q-rows). Q prescaled by 1/8.
// QK^T: 3-term hi/lo split; P,V: plain bf16. Output fp32.
#define FA_STR 144
#define FA_QH 0
#define FA_QL 9216
#define FA_K0 18432
#define FA_V0 55296
#define FA_SMEM 73728

__global__ __launch_bounds__(128)
void flash_attn_mma(const bf16* __restrict__ Qh, const bf16* __restrict__ Ql,
                    const bf16* __restrict__ Kh, const bf16* __restrict__ Kl,
                    const bf16* __restrict__ Vh, float* __restrict__ O, int S) {
    extern __shared__ char smf[];
    const uint32_t sb = smem_u32(smf);
    const int tid = threadIdx.x, lane = tid & 31, w = tid >> 5;
    const int qt = blockIdx.x, h = blockIdx.y, b = blockIdx.z;
    const int q0 = qt * 64;
    const size_t gbase = ((size_t)b * S) * D_DIM + (size_t)h * HD;

    // Q tile (group) + KV tile 0 (group)
    {
        int i = tid;
        #pragma unroll
        for (int it = 0; it < 4; ++it, i += 128) {
            int r = i >> 3, sg = i & 7;
            size_t src = gbase + (size_t)(q0 + r) * D_DIM + sg * 8;
            cp16(sb + FA_QH + r * FA_STR + sg * 16, Qh + src);
            cp16(sb + FA_QL + r * FA_STR + sg * 16, Ql + src);
        }
        CP_COMMIT();
    }
    auto issue = [&](int t) {
        const int buf = t & 1, j0 = t * 64;
        const uint32_t kb = sb + FA_K0 + buf * 18432;
        const uint32_t vb = sb + FA_V0 + buf * 9216;
        int i = tid;
        #pragma unroll
        for (int it = 0; it < 4; ++it, i += 128) {
            int r = i >> 3, sg = i & 7;
            size_t src = gbase + (size_t)(j0 + r) * D_DIM + sg * 8;
            cp16(kb + r * FA_STR + sg * 16, Kh + src);
            cp16(kb + 9216 + r * FA_STR + sg * 16, Kl + src);
            cp16(vb + r * FA_STR + sg * 16, Vh + src);
        }
        CP_COMMIT();
    };
    issue(0);
    CP_WAIT0();
    __syncthreads();

    // Q fragments (row-major A frags, same convention as gemm)
    uint32_t qh[4][4], ql[4][4];
    {
        uint32_t qb = sb + (uint32_t)(w * 16 + (lane & 15)) * FA_STR + (lane >> 4) * 16;
        #pragma unroll
        for (int kk = 0; kk < 4; ++kk) {
            ldsm4(qh[kk][0], qh[kk][1], qh[kk][2], qh[kk][3], qb + FA_QH + kk * 32);
            ldsm4(ql[kk][0], ql[kk][1], ql[kk][2], ql[kk][3], qb + FA_QL + kk * 32);
        }
    }

    float o[8][4];
    #pragma unroll
    for (int g = 0; g < 8; ++g) { o[g][0] = o[g][1] = o[g][2] = o[g][3] = 0.f; }
    float m0 = -1e30f, m1 = -1e30f, l0 = 0.f, l1 = 0.f;

    const int rA = q0 + w * 16 + (lane >> 2);
    const int cq = 2 * (lane & 3);

    for (int t = 0; t <= qt; ++t) {
        if (t > 0) { CP_WAIT0(); __syncthreads(); }
        if (t < qt) issue(t + 1);

        const int buf = t & 1;
        const uint32_t kbase = sb + FA_K0 + buf * 18432 +
                               (uint32_t)(lane & 15) * FA_STR + (lane >> 4) * 16;
        float s[8][4];
        #pragma unroll
        for (int g = 0; g < 8; ++g) { s[g][0] = s[g][1] = s[g][2] = s[g][3] = 0.f; }

        #pragma unroll
        for (int kk = 0; kk < 4; ++kk) {
            #pragma unroll
            for (int ng = 0; ng < 4; ++ng) {
                uint32_t kh0,kh1,kh2,kh3, kl0,kl1,kl2,kl3;
                uint32_t addr = kbase + (uint32_t)(ng * 16) * FA_STR + kk * 32;
                ldsm4(kh0, kh1, kh2, kh3, addr);
                ldsm4(kl0, kl1, kl2, kl3, addr + 9216);
                mma16816(s[2*ng],   qh[kk], kh0, kh2);
                mma16816(s[2*ng],   ql[kk], kh0, kh2);
                mma16816(s[2*ng],   qh[kk], kl0, kl2);
                mma16816(s[2*ng+1], qh[kk], kh1, kh3);
                mma16816(s[2*ng+1], ql[kk], kh1, kh3);
                mma16816(s[2*ng+1], qh[kk], kl1, kl3);
            }
        }

        if (t == qt) {
            #pragma unroll
            for (int g = 0; g < 8; ++g) {
                int cc = t * 64 + 8 * g + cq;
                if (cc     > rA)     s[g][0] = -1e30f;
                if (cc + 1 > rA)     s[g][1] = -1e30f;
                if (cc     > rA + 8) s[g][2] = -1e30f;
                if (cc + 1 > rA + 8) s[g][3] = -1e30f;
            }
        }

        float mr0 = -1e30f, mr1 = -1e30f;
        #pragma unroll
        for (int g = 0; g < 8; ++g) {
            mr0 = fmaxf(mr0, fmaxf(s[g][0], s[g][1]));
            mr1 = fmaxf(mr1, fmaxf(s[g][2], s[g][3]));
        }
        mr0 = fmaxf(mr0, __shfl_xor_sync(0xffffffffu, mr0, 1));
        mr0 = fmaxf(mr0, __shfl_xor_sync(0xffffffffu, mr0, 2));
        mr1 = fmaxf(mr1, __shfl_xor_sync(0xffffffffu, mr1, 1));
        mr1 = fmaxf(mr1, __shfl_xor_sync(0xffffffffu, mr1, 2));
        float mn0 = fmaxf(m0, mr0), mn1 = fmaxf(m1, mr1);
        float a0 = __expf(m0 - mn0), a1 = __expf(m1 - mn1);
        m0 = mn0; m1 = mn1;
        float ps0 = 0.f, ps1 = 0.f;
        #pragma unroll
        for (int g = 0; g < 8; ++g) {
            s[g][0] = __expf(s[g][0] - m0); s[g][1] = __expf(s[g][1] - m0);
            s[g][2] = __expf(s[g][2] - m1); s[g][3] = __expf(s[g][3] - m1);
            ps0 += s[g][0] + s[g][1];
            ps1 += s[g][2] + s[g][3];
        }
        ps0 += __shfl_xor_sync(0xffffffffu, ps0, 1);
        ps0 += __shfl_xor_sync(0xffffffffu, ps0, 2);
        ps1 += __shfl_xor_sync(0xffffffffu, ps1, 1);
        ps1 += __shfl_xor_sync(0xffffffffu, ps1, 2);
        l0 = l0 * a0 + ps0;
        l1 = l1 * a1 + ps1;
        #pragma unroll
        for (int g = 0; g < 8; ++g) {
            o[g][0] *= a0; o[g][1] *= a0; o[g][2] *= a1; o[g][3] *= a1;
        }

        // P fragments (bf16)
        uint32_t p[4][4];
        #pragma unroll
        for (int kk = 0; kk < 4; ++kk) {
            p[kk][0] = packbf(s[2*kk][0],   s[2*kk][1]);
            p[kk][1] = packbf(s[2*kk][2],   s[2*kk][3]);
            p[kk][2] = packbf(s[2*kk+1][0], s[2*kk+1][1]);
            p[kk][3] = packbf(s[2*kk+1][2], s[2*kk+1][3]);
        }

        // P @ V  (V via ldmatrix.trans)
        const uint32_t vb0 = sb + FA_V0 + buf * 9216;
        #pragma unroll
        for (int kk = 0; kk < 4; ++kk) {
            #pragma unroll
            for (int nn = 0; nn < 4; ++nn) {
                uint32_t v0, v1, v2, v3;
                uint32_t addr = vb0 + (uint32_t)(kk * 16 + (lane & 15)) * FA_STR +
                                (uint32_t)(nn * 16 + (lane >> 4) * 8) * 2;
                ldsm4t(v0, v1, v2, v3, addr);
                mma16816(o[2*nn],   p[kk], v0, v1);
                mma16816(o[2*nn+1], p[kk], v2, v3);
            }
        }
    }

    const float i0 = 1.f / l0, i1 = 1.f / l1;
    #pragma unroll
    for (int g = 0; g < 8; ++g) {
        float2 r0 = make_float2(o[g][0] * i0, o[g][1] * i0);
        float2 r1 = make_float2(o[g][2] * i1, o[g][3] * i1);
        *(float2*)(O + gbase + (size_t)rA * D_DIM + 8 * g + cq) = r0;
        *(float2*)(O + gbase + (size_t)(rA + 8) * D_DIM + 8 * g + cq) = r1;
    }
}

// ---------------- launch ----------------------------------------------------
extern "C" void kernel_launch(void* const* d_in, const int* in_sizes, int n_in,
                              void* d_out, int out_size) {
    const float* x     = (const float*)d_in[0];
    const float* wq    = (const float*)d_in[1];
    const float* wk    = (const float*)d_in[2];
    const float* wv    = (const float*)d_in[3];
    const float* wo    = (const float*)d_in[4];
    const float* w_in  = (const float*)d_in[5];
    const float* w_out = (const float*)d_in[6];
    float* out = (float*)d_out;

    const int Mtot = in_sizes[0] / D_DIM;   // 4096
    const int B = 2;
    const int S = Mtot / B;                 // 2048

    float *y, *q, *k, *v, *attn, *h, *y2, *ffn, *wt;
    cudaGetSymbolAddress((void**)&y,    g_y);
    cudaGetSymbolAddress((void**)&q,    g_q);
    cudaGetSymbolAddress((void**)&k,    g_k);
    cudaGetSymbolAddress((void**)&v,    g_v);
    cudaGetSymbolAddress((void**)&attn, g_attn);
    cudaGetSymbolAddress((void**)&h,    g_h);
    cudaGetSymbolAddress((void**)&y2,   g_y2);
    cudaGetSymbolAddress((void**)&ffn,  g_ffn);
    cudaGetSymbolAddress((void**)&wt,   g_wt);

    bf16* qhi = (bf16*)q;            bf16* qlo = qhi + 4096u * 1024u;
    bf16* khi = (bf16*)k;            bf16* klo = khi + 4096u * 1024u;
    bf16* vhi = (bf16*)v;            bf16* vlo = vhi + 4096u * 1024u;

    float* wqT    = wt;
    float* wkT    = wt + 1024u * 1024u;
    float* wvT    = wt + 2u * 1024u * 1024u;
    float* woT    = wt + 3u * 1024u * 1024u;
    float* w_inT  = wt + 4u * 1024u * 1024u;
    float* w_outT = wt + 8u * 1024u * 1024u;

    cudaFuncSetAttribute(gemm_mma<0>, cudaFuncAttributeMaxDynamicSharedMemorySize, GSMEM);
    cudaFuncSetAttribute(gemm_mma<1>, cudaFuncAttributeMaxDynamicSharedMemorySize, GSMEM);
    cudaFuncSetAttribute(gemm_mma<2>, cudaFuncAttributeMaxDynamicSharedMemorySize, GSMEM);
    cudaFuncSetAttribute(gemm_mma<3>, cudaFuncAttributeMaxDynamicSharedMemorySize, GSMEM);
    cudaFuncSetAttribute(flash_attn_mma, cudaFuncAttributeMaxDynamicSharedMemorySize, FA_SMEM);

    dim3 tb(32, 8);
    transpose_kernel<<<dim3(32, 32), tb>>>(wq, wqT, 1024, 1024);
    transpose_kernel<<<dim3(32, 32), tb>>>(wk, wkT, 1024, 1024);
    transpose_kernel<<<dim3(32, 32), tb>>>(wv, wvT, 1024, 1024);
    transpose_kernel<<<dim3(32, 32), tb>>>(wo, woT, 1024, 1024);
    transpose_kernel<<<dim3(128, 32), tb>>>(w_in, w_inT, 1024, 4096);
    transpose_kernel<<<dim3(32, 128), tb>>>(w_out, w_outT, 4096, 1024);

    // 1. y = srmsnorm(x)
    srmsnorm_kernel<<<Mtot, 256>>>(x, y);

    // 2. q,k,v = y @ w  -> bf16 hi/lo planes (q prescaled by 1/sqrt(hd))
    dim3 gD(D_DIM / 128, Mtot / 128);
    gemm_mma<3><<<gD, 256, GSMEM>>>(y, wqT, nullptr, nullptr, qhi, qlo, 0.125f, D_DIM, D_DIM);
    gemm_mma<3><<<gD, 256, GSMEM>>>(y, wkT, nullptr, nullptr, khi, klo, 1.0f,   D_DIM, D_DIM);
    gemm_mma<3><<<gD, 256, GSMEM>>>(y, wvT, nullptr, nullptr, vhi, vlo, 1.0f,   D_DIM, D_DIM);

    // 3. attention (mma flash) -> fp32
    dim3 ga(S / 64, NHEADS, B);
    flash_attn_mma<<<ga, 128, FA_SMEM>>>(qhi, qlo, khi, klo, vhi, attn, S);

    // 4. h = attn @ wo + x
    gemm_mma<2><<<gD, 256, GSMEM>>>(attn, woT, x, h, nullptr, nullptr, 1.0f, D_DIM, D_DIM);

    // 5. y2 = srmsnorm(h)
    srmsnorm_kernel<<<Mtot, 256>>>(h, y2);

    // 6. ffn = gelu(y2 @ w_in)
    dim3 gF(F_DIM / 128, Mtot / 128);
    gemm_mma<1><<<gF, 256, GSMEM>>>(y2, w_inT, nullptr, ffn, nullptr, nullptr, 1.0f, F_DIM, D_DIM);

    // 7. out = ffn @ w_out + h
    gemm_mma<2><<<gD, 256, GSMEM>>>(ffn, w_outT, h, out, nullptr, nullptr, 1.0f, D_DIM, F_DIM);
}

// round 15
// speedup vs baseline: 1.8427x; 1.0106x over previous
#include <cuda_runtime.h>
#include <cuda_bf16.h>
#include <math.h>
#include <stdint.h>

#define D_DIM 1024
#define F_DIM 4096
#define NHEADS 16
#define HD 64

typedef __nv_bfloat16 bf16;
typedef __nv_bfloat162 bf162;

// ---------------- scratch (no cudaMalloc allowed) ----------------
__device__ float g_y   [4096u * 1024u];
// qkv bf16 planes: [qhi,qlo,khi,klo,vhi,vlo] each 4096x1024
__device__ __align__(256) bf16 g_qkv [6u * 4096u * 1024u];
__device__ float g_attn[4096u * 1024u];
__device__ float g_h   [4096u * 1024u];
__device__ float g_y2  [4096u * 1024u];
__device__ float g_ffn [4096u * 4096u];
__device__ float g_wt  [12u * 1024u * 1024u];

// ======================= helpers =======================
__device__ __forceinline__ uint32_t smem_u32(const void* p) {
    uint32_t a;
    asm("{ .reg .u64 t; cvta.to.shared.u64 t, %1; cvt.u32.u64 %0, t; }" : "=r"(a) : "l"(p));
    return a;
}
__device__ __forceinline__ void cp16(uint32_t dst, const void* src) {
    asm volatile("cp.async.cg.shared.global [%0], [%1], 16;" :: "r"(dst), "l"(src) : "memory");
}
#define CP_COMMIT() asm volatile("cp.async.commit_group;" ::: "memory")
#define CP_WAIT0()  asm volatile("cp.async.wait_group 0;" ::: "memory")
__device__ __forceinline__ void ldsm4(uint32_t& r0, uint32_t& r1, uint32_t& r2, uint32_t& r3,
                                      uint32_t addr) {
    asm volatile("ldmatrix.sync.aligned.m8n8.x4.shared.b16 {%0,%1,%2,%3}, [%4];"
                 : "=r"(r0), "=r"(r1), "=r"(r2), "=r"(r3) : "r"(addr));
}
__device__ __forceinline__ void ldsm4t(uint32_t& r0, uint32_t& r1, uint32_t& r2, uint32_t& r3,
                                       uint32_t addr) {
    asm volatile("ldmatrix.sync.aligned.m8n8.x4.trans.shared.b16 {%0,%1,%2,%3}, [%4];"
                 : "=r"(r0), "=r"(r1), "=r"(r2), "=r"(r3) : "r"(addr));
}
__device__ __forceinline__ void mma16816(float* d, const uint32_t* a, uint32_t b0, uint32_t b1) {
    asm volatile(
        "mma.sync.aligned.m16n8k16.row.col.f32.bf16.bf16.f32 "
        "{%0,%1,%2,%3}, {%4,%5,%6,%7}, {%8,%9}, {%0,%1,%2,%3};"
        : "+f"(d[0]), "+f"(d[1]), "+f"(d[2]), "+f"(d[3])
        : "r"(a[0]), "r"(a[1]), "r"(a[2]), "r"(a[3]), "r"(b0), "r"(b1));
}
__device__ __forceinline__ void split4(float4 v, uint2& hi, uint2& lo) {
    bf162 h01 = __floats2bfloat162_rn(v.x, v.y);
    bf162 h23 = __floats2bfloat162_rn(v.z, v.w);
    float2 f01 = __bfloat1622float2(h01);
    float2 f23 = __bfloat1622float2(h23);
    bf162 l01 = __floats2bfloat162_rn(v.x - f01.x, v.y - f01.y);
    bf162 l23 = __floats2bfloat162_rn(v.z - f23.x, v.w - f23.y);
    hi.x = *(uint32_t*)&h01; hi.y = *(uint32_t*)&h23;
    lo.x = *(uint32_t*)&l01; lo.y = *(uint32_t*)&l23;
}
__device__ __forceinline__ void split2(float x, float y, uint32_t& hi, uint32_t& lo) {
    bf162 h = __floats2bfloat162_rn(x, y);
    float2 f = __bfloat1622float2(h);
    bf162 l = __floats2bfloat162_rn(x - f.x, y - f.y);
    hi = *(uint32_t*)&h; lo = *(uint32_t*)&l;
}
__device__ __forceinline__ uint32_t packbf(float a, float b) {
    bf162 h = __floats2bfloat162_rn(a, b);
    return *(uint32_t*)&h;
}
__device__ __forceinline__ float gelu_tanh(float x) {
    float x3 = x * x * x;
    float t = tanhf(0.7978845608028654f * (x + 0.044715f * x3));
    return 0.5f * x * (1.0f + t);
}

// ---------------- srmsnorm (fp32 out) ----------------
__global__ __launch_bounds__(256)
void srmsnorm_kernel(const float* __restrict__ x, float* __restrict__ y) {
    const int row = blockIdx.x;
    const float4* xr = (const float4*)(x + (size_t)row * D_DIM);
    float4 v = xr[threadIdx.x];
    float ss = v.x * v.x + v.y * v.y + v.z * v.z + v.w * v.w;
    #pragma unroll
    for (int o = 16; o > 0; o >>= 1) ss += __shfl_xor_sync(0xffffffffu, ss, o);
    __shared__ float ws[8];
    if ((threadIdx.x & 31) == 0) ws[threadIdx.x >> 5] = ss;
    __syncthreads();
    float tot = ws[0] + ws[1] + ws[2] + ws[3] + ws[4] + ws[5] + ws[6] + ws[7];
    float s = 32.0f / fmaxf(sqrtf(tot), 1e-12f);
    float4* yr = (float4*)(y + (size_t)row * D_DIM);
    v.x *= s; v.y *= s; v.z *= s; v.w *= s;
    yr[threadIdx.x] = v;
}

// ---------------- transpose ----------------
__global__ __launch_bounds__(256)
void transpose_kernel(const float* __restrict__ src, float* __restrict__ dst, int R, int C) {
    __shared__ float t[32][33];
    int bx = blockIdx.x * 32, by = blockIdx.y * 32;
    #pragma unroll
    for (int j = 0; j < 32; j += 8)
        t[threadIdx.y + j][threadIdx.x] = src[(size_t)(by + threadIdx.y + j) * C + bx + threadIdx.x];
    __syncthreads();
    #pragma unroll
    for (int j = 0; j < 32; j += 8)
        dst[(size_t)(bx + threadIdx.y + j) * R + by + threadIdx.x] = t[threadIdx.x][threadIdx.y + j];
}

// ============== HMMA bf16 hi/lo split GEMM ==============
// EPI: 0 fp32 out; 1 gelu fp32 out; 2 fp32 out + residual R; 4 fused qkv -> planes
#define ASTR 144
#define TILEB (128 * ASTR)
#define GSMEM (4 * TILEB)   // 73728

template<int EPI>
__global__ __launch_bounds__(256)
void gemm_mma(const float* __restrict__ A, const float* __restrict__ Bt,
              const float* __restrict__ R, float* __restrict__ C,
              bf16* __restrict__ QKV,
              int Nd, int Kd) {
    extern __shared__ char smem[];
    const uint32_t sbase = smem_u32(smem);
    const int tid = threadIdx.x;
    const int lane = tid & 31, wid = tid >> 5;
    const int row0 = blockIdx.y * 128, col0 = blockIdx.x * 128;
    const int wm0 = (wid >> 2) * 64;
    const int wn0 = (wid & 3) * 32;

    const uint32_t SA[2] = { sbase,         sbase + 2 * TILEB };
    const uint32_t SB[2] = { sbase + TILEB, sbase + 3 * TILEB };

    float c[16][4];
    #pragma unroll
    for (int i = 0; i < 16; ++i)
        #pragma unroll
        for (int j = 0; j < 4; ++j) c[i][j] = 0.f;

    const int gr = tid >> 3;
    const int gq = tid & 7;
    const float* Agl = A  + (size_t)(row0 + gr) * Kd + gq * 4;
    const float* Bgl = Bt + (size_t)(col0 + gr) * Kd + gq * 4;

    float4 va[4], vb[4];
    auto ldg = [&](int s) {
        const int k0 = s * 32;
        #pragma unroll
        for (int i = 0; i < 4; ++i) {
            va[i] = *(const float4*)(Agl + (size_t)(i * 32) * Kd + k0);
            vb[i] = *(const float4*)(Bgl + (size_t)(i * 32) * Kd + k0);
        }
    };
    auto sts = [&](int b) {
        char* da = smem + (b ? 2 * TILEB : 0);
        char* db = smem + (b ? 3 * TILEB : TILEB);
        #pragma unroll
        for (int i = 0; i < 4; ++i) {
            uint2 hi, lo;
            int off = (gr + i * 32) * ASTR + gq * 8;
            split4(va[i], hi, lo);
            *(uint2*)(da + off) = hi;
            *(uint2*)(da + off + 64) = lo;
            split4(vb[i], hi, lo);
            *(uint2*)(db + off) = hi;
            *(uint2*)(db + off + 64) = lo;
        }
    };

    const uint32_t lrow = (uint32_t)(lane & 15) * ASTR;
    const uint32_t lk   = (uint32_t)(lane >> 4) * 16;
    const int stages = Kd / 32;

    ldg(0); sts(0); __syncthreads();

    for (int s = 0; s < stages; ++s) {
        const int b = s & 1;
        if (s + 1 < stages) ldg(s + 1);

        const uint32_t Ab = SA[b] + lrow + lk;
        const uint32_t Bb = SB[b] + lrow + lk;
        #pragma unroll
        for (int kk = 0; kk < 2; ++kk) {
            const uint32_t kb = kk * 32;
            uint32_t ah[16], al[16], bh[8], bl[8];
            #pragma unroll
            for (int mt = 0; mt < 4; ++mt)
                ldsm4(ah[4*mt], ah[4*mt+1], ah[4*mt+2], ah[4*mt+3],
                      Ab + (uint32_t)(wm0 + mt * 16) * ASTR + kb);
            #pragma unroll
            for (int g = 0; g < 2; ++g)
                ldsm4(bh[4*g], bh[4*g+1], bh[4*g+2], bh[4*g+3],
                      Bb + (uint32_t)(wn0 + g * 16) * ASTR + kb);
            #pragma unroll
            for (int mt = 0; mt < 4; ++mt)
                #pragma unroll
                for (int nt = 0; nt < 4; ++nt) {
                    int bi = 4 * (nt >> 1) + (nt & 1);
                    mma16816(c[mt * 4 + nt], &ah[4 * mt], bh[bi], bh[bi + 2]);
                }
            #pragma unroll
            for (int mt = 0; mt < 4; ++mt)
                ldsm4(al[4*mt], al[4*mt+1], al[4*mt+2], al[4*mt+3],
                      Ab + (uint32_t)(wm0 + mt * 16) * ASTR + 64 + kb);
            #pragma unroll
            for (int mt = 0; mt < 4; ++mt)
                #pragma unroll
                for (int nt = 0; nt < 4; ++nt) {
                    int bi = 4 * (nt >> 1) + (nt & 1);
                    mma16816(c[mt * 4 + nt], &al[4 * mt], bh[bi], bh[bi + 2]);
                }
            #pragma unroll
            for (int g = 0; g < 2; ++g)
                ldsm4(bl[4*g], bl[4*g+1], bl[4*g+2], bl[4*g+3],
                      Bb + (uint32_t)(wn0 + g * 16) * ASTR + 64 + kb);
            #pragma unroll
            for (int mt = 0; mt < 4; ++mt)
                #pragma unroll
                for (int nt = 0; nt < 4; ++nt) {
                    int bi = 4 * (nt >> 1) + (nt & 1);
                    mma16816(c[mt * 4 + nt], &ah[4 * mt], bl[bi], bl[bi + 2]);
                }
        }
        // single sync per stage: sts writes the OTHER buffer; the previous
        // iteration's sync already drained all readers of it.
        if (s + 1 < stages) sts(b ^ 1);
        __syncthreads();
    }

    const int mrow = row0 + wm0 + (lane >> 2);
    #pragma unroll
    for (int mt = 0; mt < 4; ++mt)
        #pragma unroll
        for (int nt = 0; nt < 4; ++nt) {
            const float* cc = c[mt * 4 + nt];
            const int m0 = mrow + mt * 16;
            if (EPI == 4) {
                // fused qkv: select plane pair + scale by global column
                const int sel = col0 >> 10;              // 0=q, 1=k, 2=v
                bf16* Chi = QKV + (size_t)(2 * sel) * (4096u * 1024u);
                bf16* Clo = Chi + 4096u * 1024u;
                const float scale = (sel == 0) ? 0.125f : 1.0f;
                const int n = (col0 & 1023) + wn0 + nt * 8 + 2 * (lane & 3);
                uint32_t h0, l0, h1, l1;
                split2(cc[0] * scale, cc[1] * scale, h0, l0);
                split2(cc[2] * scale, cc[3] * scale, h1, l1);
                *(uint32_t*)(Chi + (size_t)m0 * 1024 + n) = h0;
                *(uint32_t*)(Clo + (size_t)m0 * 1024 + n) = l0;
                *(uint32_t*)(Chi + (size_t)(m0 + 8) * 1024 + n) = h1;
                *(uint32_t*)(Clo + (size_t)(m0 + 8) * 1024 + n) = l1;
            } else {
                const int n = col0 + wn0 + nt * 8 + 2 * (lane & 3);
                float2 r0 = make_float2(cc[0], cc[1]);
                float2 r1 = make_float2(cc[2], cc[3]);
                if (EPI == 1) {
                    r0.x = gelu_tanh(r0.x); r0.y = gelu_tanh(r0.y);
                    r1.x = gelu_tanh(r1.x); r1.y = gelu_tanh(r1.y);
                }
                if (EPI == 2) {
                    float2 a0 = *(const float2*)(R + (size_t)m0 * Nd + n);
                    float2 a1 = *(const float2*)(R + (size_t)(m0 + 8) * Nd + n);
                    r0.x += a0.x; r0.y += a0.y;
                    r1.x += a1.x; r1.y += a1.y;
                }
                *(float2*)(C + (size_t)m0 * Nd + n) = r0;
                *(float2*)(C + (size_t)(m0 + 8) * Nd + n) = r1;
            }
        }
}

// ================= mma causal flash attention =================
// grid (S/64, H, B), 128 thr (4 warps x 16 q-rows). Q prescaled by 1/8.
// QK^T: 3-term hi/lo split; P,V: plain bf16. Output fp32.
#define FA_STR 144
#define FA_QH 0
#define FA_QL 9216
#define FA_K0 18432
#define FA_V0 55296
#define FA_SMEM 73728

__global__ __launch_bounds__(128)
void flash_attn_mma(const bf16* __restrict__ Qh, const bf16* __restrict__ Ql,
                    const bf16* __restrict__ Kh, const bf16* __restrict__ Kl,
                    const bf16* __restrict__ Vh, float* __restrict__ O, int S) {
    extern __shared__ char smf[];
    const uint32_t sb = smem_u32(smf);
    const int tid = threadIdx.x, lane = tid & 31, w = tid >> 5;
    const int qt = blockIdx.x, h = blockIdx.y, b = blockIdx.z;
    const int q0 = qt * 64;
    const size_t gbase = ((size_t)b * S) * D_DIM + (size_t)h * HD;

    {
        int i = tid;
        #pragma unroll
        for (int it = 0; it < 4; ++it, i += 128) {
            int r = i >> 3, sg = i & 7;
            size_t src = gbase + (size_t)(q0 + r) * D_DIM + sg * 8;
            cp16(sb + FA_QH + r * FA_STR + sg * 16, Qh + src);
            cp16(sb + FA_QL + r * FA_STR + sg * 16, Ql + src);
        }
        CP_COMMIT();
    }
    auto issue = [&](int t) {
        const int buf = t & 1, j0 = t * 64;
        const uint32_t kb = sb + FA_K0 + buf * 18432;
        const uint32_t vb = sb + FA_V0 + buf * 9216;
        int i = tid;
        #pragma unroll
        for (int it = 0; it < 4; ++it, i += 128) {
            int r = i >> 3, sg = i & 7;
            size_t src = gbase + (size_t)(j0 + r) * D_DIM + sg * 8;
            cp16(kb + r * FA_STR + sg * 16, Kh + src);
            cp16(kb + 9216 + r * FA_STR + sg * 16, Kl + src);
            cp16(vb + r * FA_STR + sg * 16, Vh + src);
        }
        CP_COMMIT();
    };
    issue(0);
    CP_WAIT0();
    __syncthreads();

    uint32_t qh[4][4], ql[4][4];
    {
        uint32_t qb = sb + (uint32_t)(w * 16 + (lane & 15)) * FA_STR + (lane >> 4) * 16;
        #pragma unroll
        for (int kk = 0; kk < 4; ++kk) {
            ldsm4(qh[kk][0], qh[kk][1], qh[kk][2], qh[kk][3], qb + FA_QH + kk * 32);
            ldsm4(ql[kk][0], ql[kk][1], ql[kk][2], ql[kk][3], qb + FA_QL + kk * 32);
        }
    }

    float o[8][4];
    #pragma unroll
    for (int g = 0; g < 8; ++g) { o[g][0] = o[g][1] = o[g][2] = o[g][3] = 0.f; }
    float m0 = -1e30f, m1 = -1e30f, l0 = 0.f, l1 = 0.f;

    const int rA = q0 + w * 16 + (lane >> 2);
    const int cq = 2 * (lane & 3);

    for (int t = 0; t <= qt; ++t) {
        if (t > 0) { CP_WAIT0(); __syncthreads(); }
        if (t < qt) issue(t + 1);

        const int buf = t & 1;
        const uint32_t kbase = sb + FA_K0 + buf * 18432 +
                               (uint32_t)(lane & 15) * FA_STR + (lane >> 4) * 16;
        float s[8][4];
        #pragma unroll
        for (int g = 0; g < 8; ++g) { s[g][0] = s[g][1] = s[g][2] = s[g][3] = 0.f; }

        #pragma unroll
        for (int kk = 0; kk < 4; ++kk) {
            #pragma unroll
            for (int ng = 0; ng < 4; ++ng) {
                uint32_t kh0,kh1,kh2,kh3, kl0,kl1,kl2,kl3;
                uint32_t addr = kbase + (uint32_t)(ng * 16) * FA_STR + kk * 32;
                ldsm4(kh0, kh1, kh2, kh3, addr);
                ldsm4(kl0, kl1, kl2, kl3, addr + 9216);
                mma16816(s[2*ng],   qh[kk], kh0, kh2);
                mma16816(s[2*ng],   ql[kk], kh0, kh2);
                mma16816(s[2*ng],   qh[kk], kl0, kl2);
                mma16816(s[2*ng+1], qh[kk], kh1, kh3);
                mma16816(s[2*ng+1], ql[kk], kh1, kh3);
                mma16816(s[2*ng+1], qh[kk], kl1, kl3);
            }
        }

        if (t == qt) {
            #pragma unroll
            for (int g = 0; g < 8; ++g) {
                int cc = t * 64 + 8 * g + cq;
                if (cc     > rA)     s[g][0] = -1e30f;
                if (cc + 1 > rA)     s[g][1] = -1e30f;
                if (cc     > rA + 8) s[g][2] = -1e30f;
                if (cc + 1 > rA + 8) s[g][3] = -1e30f;
            }
        }

        float mr0 = -1e30f, mr1 = -1e30f;
        #pragma unroll
        for (int g = 0; g < 8; ++g) {
            mr0 = fmaxf(mr0, fmaxf(s[g][0], s[g][1]));
            mr1 = fmaxf(mr1, fmaxf(s[g][2], s[g][3]));
        }
        mr0 = fmaxf(mr0, __shfl_xor_sync(0xffffffffu, mr0, 1));
        mr0 = fmaxf(mr0, __shfl_xor_sync(0xffffffffu, mr0, 2));
        mr1 = fmaxf(mr1, __shfl_xor_sync(0xffffffffu, mr1, 1));
        mr1 = fmaxf(mr1, __shfl_xor_sync(0xffffffffu, mr1, 2));
        float mn0 = fmaxf(m0, mr0), mn1 = fmaxf(m1, mr1);
        float a0 = __expf(m0 - mn0), a1 = __expf(m1 - mn1);
        m0 = mn0; m1 = mn1;
        float ps0 = 0.f, ps1 = 0.f;
        #pragma unroll
        for (int g = 0; g < 8; ++g) {
            s[g][0] = __expf(s[g][0] - m0); s[g][1] = __expf(s[g][1] - m0);
            s[g][2] = __expf(s[g][2] - m1); s[g][3] = __expf(s[g][3] - m1);
            ps0 += s[g][0] + s[g][1];
            ps1 += s[g][2] + s[g][3];
        }
        ps0 += __shfl_xor_sync(0xffffffffu, ps0, 1);
        ps0 += __shfl_xor_sync(0xffffffffu, ps0, 2);
        ps1 += __shfl_xor_sync(0xffffffffu, ps1, 1);
        ps1 += __shfl_xor_sync(0xffffffffu, ps1, 2);
        l0 = l0 * a0 + ps0;
        l1 = l1 * a1 + ps1;
        #pragma unroll
        for (int g = 0; g < 8; ++g) {
            o[g][0] *= a0; o[g][1] *= a0; o[g][2] *= a1; o[g][3] *= a1;
        }

        uint32_t p[4][4];
        #pragma unroll
        for (int kk = 0; kk < 4; ++kk) {
            p[kk][0] = packbf(s[2*kk][0],   s[2*kk][1]);
            p[kk][1] = packbf(s[2*kk][2],   s[2*kk][3]);
            p[kk][2] = packbf(s[2*kk+1][0], s[2*kk+1][1]);
            p[kk][3] = packbf(s[2*kk+1][2], s[2*kk+1][3]);
        }

        const uint32_t vb0 = sb + FA_V0 + buf * 9216;
        #pragma unroll
        for (int kk = 0; kk < 4; ++kk) {
            #pragma unroll
            for (int nn = 0; nn < 4; ++nn) {
                uint32_t v0, v1, v2, v3;
                uint32_t addr = vb0 + (uint32_t)(kk * 16 + (lane & 15)) * FA_STR +
                                (uint32_t)(nn * 16 + (lane >> 4) * 8) * 2;
                ldsm4t(v0, v1, v2, v3, addr);
                mma16816(o[2*nn],   p[kk], v0, v1);
                mma16816(o[2*nn+1], p[kk], v2, v3);
            }
        }
    }

    const float i0 = 1.f / l0, i1 = 1.f / l1;
    #pragma unroll
    for (int g = 0; g < 8; ++g) {
        float2 r0 = make_float2(o[g][0] * i0, o[g][1] * i0);
        float2 r1 = make_float2(o[g][2] * i1, o[g][3] * i1);
        *(float2*)(O + gbase + (size_t)rA * D_DIM + 8 * g + cq) = r0;
        *(float2*)(O + gbase + (size_t)(rA + 8) * D_DIM + 8 * g + cq) = r1;
    }
}

// ---------------- launch ----------------------------------------------------
extern "C" void kernel_launch(void* const* d_in, const int* in_sizes, int n_in,
                              void* d_out, int out_size) {
    const float* x     = (const float*)d_in[0];
    const float* wq    = (const float*)d_in[1];
    const float* wk    = (const float*)d_in[2];
    const float* wv    = (const float*)d_in[3];
    const float* wo    = (const float*)d_in[4];
    const float* w_in  = (const float*)d_in[5];
    const float* w_out = (const float*)d_in[6];
    float* out = (float*)d_out;

    const int Mtot = in_sizes[0] / D_DIM;   // 4096
    const int B = 2;
    const int S = Mtot / B;                 // 2048

    float *y, *attn, *h, *y2, *ffn, *wt;
    bf16* qkv;
    cudaGetSymbolAddress((void**)&y,    g_y);
    cudaGetSymbolAddress((void**)&qkv,  g_qkv);
    cudaGetSymbolAddress((void**)&attn, g_attn);
    cudaGetSymbolAddress((void**)&h,    g_h);
    cudaGetSymbolAddress((void**)&y2,   g_y2);
    cudaGetSymbolAddress((void**)&ffn,  g_ffn);
    cudaGetSymbolAddress((void**)&wt,   g_wt);

    const size_t PL = 4096u * 1024u;
    bf16 *qhi = qkv,          *qlo = qkv + PL;
    bf16 *khi = qkv + 2 * PL, *klo = qkv + 3 * PL;
    bf16 *vhi = qkv + 4 * PL;

    float* wqkvT  = wt;                        // [3072][1024] contiguous
    float* woT    = wt + 3u * 1024u * 1024u;
    float* w_inT  = wt + 4u * 1024u * 1024u;
    float* w_outT = wt + 8u * 1024u * 1024u;

    cudaFuncSetAttribute(gemm_mma<1>, cudaFuncAttributeMaxDynamicSharedMemorySize, GSMEM);
    cudaFuncSetAttribute(gemm_mma<2>, cudaFuncAttributeMaxDynamicSharedMemorySize, GSMEM);
    cudaFuncSetAttribute(gemm_mma<4>, cudaFuncAttributeMaxDynamicSharedMemorySize, GSMEM);
    cudaFuncSetAttribute(flash_attn_mma, cudaFuncAttributeMaxDynamicSharedMemorySize, FA_SMEM);

    dim3 tb(32, 8);
    transpose_kernel<<<dim3(32, 32), tb>>>(wq, wqkvT, 1024, 1024);
    transpose_kernel<<<dim3(32, 32), tb>>>(wk, wqkvT + 1024u * 1024u, 1024, 1024);
    transpose_kernel<<<dim3(32, 32), tb>>>(wv, wqkvT + 2u * 1024u * 1024u, 1024, 1024);
    transpose_kernel<<<dim3(32, 32), tb>>>(wo, woT, 1024, 1024);
    transpose_kernel<<<dim3(128, 32), tb>>>(w_in, w_inT, 1024, 4096);
    transpose_kernel<<<dim3(32, 128), tb>>>(w_out, w_outT, 4096, 1024);

    // 1. y = srmsnorm(x)
    srmsnorm_kernel<<<Mtot, 256>>>(x, y);

    // 2. fused qkv = y @ [wq|wk|wv]  -> bf16 hi/lo planes (q prescaled)
    dim3 gQKV(3 * D_DIM / 128, Mtot / 128);   // (24, 32)
    gemm_mma<4><<<gQKV, 256, GSMEM>>>(y, wqkvT, nullptr, nullptr, qkv, D_DIM, D_DIM);

    // 3. attention (mma flash) -> fp32
    dim3 ga(S / 64, NHEADS, B);
    flash_attn_mma<<<ga, 128, FA_SMEM>>>(qhi, qlo, khi, klo, vhi, attn, S);

    // 4. h = attn @ wo + x
    dim3 gD(D_DIM / 128, Mtot / 128);
    gemm_mma<2><<<gD, 256, GSMEM>>>(attn, woT, x, h, nullptr, D_DIM, D_DIM);

    // 5. y2 = srmsnorm(h)
    srmsnorm_kernel<<<Mtot, 256>>>(h, y2);

    // 6. ffn = gelu(y2 @ w_in)
    dim3 gF(F_DIM / 128, Mtot / 128);
    gemm_mma<1><<<gF, 256, GSMEM>>>(y2, w_inT, nullptr, ffn, nullptr, F_DIM, D_DIM);

    // 7. out = ffn @ w_out + h
    gemm_mma<2><<<gD, 256, GSMEM>>>(ffn, w_outT, h, out, nullptr, D_DIM, F_DIM);
}